// round 2
// baseline (speedup 1.0000x reference)
#include <cuda_runtime.h>
#include <cstdint>

// BP-MLL loss, B=8192 rows x L=10000 cols, fp32 input, int32 target in {0,1}.
//   row value = (sum_{t==1} exp(-x)) * (sum_{t==0} exp(x)) / (n_pos * n_neg)
//   output    = sum over rows (scalar).
//
// Pass 1: one CTA per row -> per-row value into __device__ scratch (no alloc).
// Pass 2: one CTA deterministic sum of 8192 row values -> d_out[0].
// Graph-capturable: two plain kernel launches, no sync, no alloc, no memcpy.

#define ROWS_MAX 8192
#define L_COLS   10000
#define VEC      (L_COLS / 4)   // 2500 float4 / int4 per row
#define BLK      256

__device__ float g_row_vals[ROWS_MAX];

__device__ __forceinline__ float warp_sum(float v) {
    #pragma unroll
    for (int o = 16; o > 0; o >>= 1)
        v += __shfl_down_sync(0xffffffffu, v, o);
    return v;
}
__device__ __forceinline__ int warp_sum_i(int v) {
    #pragma unroll
    for (int o = 16; o > 0; o >>= 1)
        v += __shfl_down_sync(0xffffffffu, v, o);
    return v;
}

__global__ void __launch_bounds__(BLK)
bpmll_row_kernel(const float* __restrict__ x,
                 const int*   __restrict__ t)
{
    const int row = blockIdx.x;
    const float4* __restrict__ xr =
        reinterpret_cast<const float4*>(x + (size_t)row * L_COLS);
    const int4* __restrict__ tr =
        reinterpret_cast<const int4*>(t + (size_t)row * L_COLS);

    float tot = 0.0f;  // sum over all elems of exp(sign-folded x)  (= sp + sn)
    float sp  = 0.0f;  // sum over positives of exp(-x)
    int   np  = 0;     // positive count

    for (int i = threadIdx.x; i < VEC; i += BLK) {
        const float4 xv = xr[i];
        const int4   tv = tr[i];

        // y = (t==1) ? -x : x  via sign-bit XOR (IMAD + LOP3), one exp each.
        {
            const unsigned s = (unsigned)tv.x * 0x80000000u;
            const float e = __expf(__int_as_float(__float_as_int(xv.x) ^ s));
            tot += e;  sp += tv.x ? e : 0.0f;
        }
        {
            const unsigned s = (unsigned)tv.y * 0x80000000u;
            const float e = __expf(__int_as_float(__float_as_int(xv.y) ^ s));
            tot += e;  sp += tv.y ? e : 0.0f;
        }
        {
            const unsigned s = (unsigned)tv.z * 0x80000000u;
            const float e = __expf(__int_as_float(__float_as_int(xv.z) ^ s));
            tot += e;  sp += tv.z ? e : 0.0f;
        }
        {
            const unsigned s = (unsigned)tv.w * 0x80000000u;
            const float e = __expf(__int_as_float(__float_as_int(xv.w) ^ s));
            tot += e;  sp += tv.w ? e : 0.0f;
        }
        np += (tv.x + tv.y) + (tv.z + tv.w);
    }

    // Block reduction: warp shuffle, then warp 0 over per-warp partials.
    __shared__ float s_tot[BLK / 32];
    __shared__ float s_sp[BLK / 32];
    __shared__ int   s_np[BLK / 32];

    const int lane = threadIdx.x & 31;
    const int wid  = threadIdx.x >> 5;

    tot = warp_sum(tot);
    sp  = warp_sum(sp);
    np  = warp_sum_i(np);
    if (lane == 0) { s_tot[wid] = tot; s_sp[wid] = sp; s_np[wid] = np; }
    __syncthreads();

    if (wid == 0) {
        tot = (lane < BLK / 32) ? s_tot[lane] : 0.0f;
        sp  = (lane < BLK / 32) ? s_sp[lane]  : 0.0f;
        np  = (lane < BLK / 32) ? s_np[lane]  : 0;
        tot = warp_sum(tot);
        sp  = warp_sum(sp);
        np  = warp_sum_i(np);
        if (lane == 0) {
            const float sn = tot - sp;
            const float k  = (float)np * (float)(L_COLS - np);
            g_row_vals[row] = sp * sn / k;
        }
    }
}

__global__ void __launch_bounds__(1024)
bpmll_reduce_kernel(float* __restrict__ out, int n)
{
    float s = 0.0f;
    for (int i = threadIdx.x; i < n; i += 1024)
        s += g_row_vals[i];

    __shared__ float sm[32];
    const int lane = threadIdx.x & 31;
    const int wid  = threadIdx.x >> 5;
    s = warp_sum(s);
    if (lane == 0) sm[wid] = s;
    __syncthreads();
    if (wid == 0) {
        s = sm[lane];
        s = warp_sum(s);
        if (lane == 0) out[0] = s;
    }
}

extern "C" void kernel_launch(void* const* d_in, const int* in_sizes, int n_in,
                              void* d_out, int out_size)
{
    const float* x = (const float*)d_in[0];
    const int*   t = (const int*)d_in[1];
    float* out = (float*)d_out;

    const int rows = in_sizes[0] / L_COLS;   // 8192

    bpmll_row_kernel<<<rows, BLK>>>(x, t);
    bpmll_reduce_kernel<<<1, 1024>>>(out, rows);
}